// round 3
// baseline (speedup 1.0000x reference)
#include <cuda_runtime.h>

#define NN 50000
#define NE 1600000
#define F 64
#define DIN 256
#define HEADS 4

// Scratch (device globals — no allocations allowed)
__device__ int g_is64;
__device__ __align__(16) int   g_row[NE];
__device__ __align__(16) int   g_col[NE];
__device__ __align__(16) float g_deg[NN];
__device__ __align__(16) float g_dinv[NN];
__device__ __align__(16) float g_xs[NN * F];   // x0 * dinv[src]
__device__ __align__(16) float g_agg[NN * F];  // aggregated features

// ---------------------------------------------------------------------------
// K0a: sniff edge_index dtype. int64 little-endian values < 2^31 have all odd
// 32-bit words == 0; int32 edge data has random node ids there.
__global__ void k_sniff(const int* __restrict__ ei32) {
    __shared__ int nz;
    if (threadIdx.x == 0) nz = 0;
    __syncthreads();
    // sample 256 odd words from the first 512 int32 words (within 2KB -> always in-bounds)
    if (ei32[2 * threadIdx.x + 1] != 0) atomicAdd(&nz, 1);
    __syncthreads();
    if (threadIdx.x == 0) g_is64 = (nz < 8) ? 1 : 0;
}

// K0b: normalize edge index to int32 row/col arrays (branch is uniform)
__global__ void k_convert(const void* __restrict__ ei) {
    int i = blockIdx.x * blockDim.x + threadIdx.x;
    if (i >= NE) return;
    int r, c;
    if (g_is64) {
        const long long* p = (const long long*)ei;
        r = (int)p[i];
        c = (int)p[NE + i];
    } else {
        const int* p = (const int*)ei;
        r = p[i];
        c = p[NE + i];
    }
    // defensive clamp: wrong dtype guess -> wrong answer (measurable), not a crash
    r = min(max(r, 0), NN - 1);
    c = min(max(c, 0), NN - 1);
    g_row[i] = r;
    g_col[i] = c;
}

// K1: deg init to 1.0 (self-loop)
__global__ void k_deg_init() {
    int i = blockIdx.x * blockDim.x + threadIdx.x;
    if (i < NN) g_deg[i] = 1.0f;
}

// K2: deg count via scalar RED (in-degree on col)
__global__ void k_deg_count() {
    int i = blockIdx.x * blockDim.x + threadIdx.x;
    if (i < NE) atomicAdd(&g_deg[g_col[i]], 1.0f);  // return unused -> RED.F32
}

// K3: dinv = rsqrt(deg); xs = x0*dinv; agg = xs*dinv (self-loop term)
// one thread per (node, float4-chunk): NN*16 threads
__global__ void k_prep(const float* __restrict__ x) {
    int i = blockIdx.x * blockDim.x + threadIdx.x;
    if (i >= NN * 16) return;
    int v = i >> 4, j = i & 15;
    float dinv = rsqrtf(g_deg[v]);
    if (j == 0) g_dinv[v] = dinv;
    float4 xv = *(const float4*)(x + (size_t)v * DIN + j * 4);
    float4 xs;
    xs.x = xv.x * dinv; xs.y = xv.y * dinv; xs.z = xv.z * dinv; xs.w = xv.w * dinv;
    *(float4*)(g_xs + (size_t)v * F + j * 4) = xs;
    float4 ag;
    ag.x = xs.x * dinv; ag.y = xs.y * dinv; ag.z = xs.z * dinv; ag.w = xs.w * dinv;
    *(float4*)(g_agg + (size_t)v * F + j * 4) = ag;
}

// K4: edge scatter. 16 threads per edge; each thread handles one float4.
// agg[col] += xs[row] * dinv[col]   (vector RED, sm_90+)
__global__ void k_scatter() {
    int t = blockIdx.x * blockDim.x + threadIdx.x;
    int e = t >> 4;
    if (e >= NE) return;
    int j = t & 15;
    int r = g_row[e];
    int c = g_col[e];
    float s = g_dinv[c];
    float4 m = *(const float4*)(g_xs + (size_t)r * F + j * 4);
    float* dst = g_agg + (size_t)c * F + j * 4;
    asm volatile("red.global.add.v4.f32 [%0], {%1, %2, %3, %4};"
                 :: "l"(dst), "f"(m.x * s), "f"(m.y * s), "f"(m.z * s), "f"(m.w * s)
                 : "memory");
}

// K5: heads = relu(agg @ W[h] + b[h]); write to x_cat region and (if present)
// duplicate to heads region. One head per blockIdx.y; 64 nodes per block.
#define NPB 64
#define AST 68  // padded agg tile stride (floats); kills stride-64 bank conflicts
__global__ void k_gemm(const float* __restrict__ W, const float* __restrict__ b,
                       float* __restrict__ out, int dual) {
    __shared__ __align__(16) float Ws[64 * 64];
    __shared__ __align__(16) float aggs[NPB * AST];
    int h = blockIdx.y;
    int n0 = blockIdx.x * NPB;
    int tid = threadIdx.x;

    // load W[h] (16KB) into smem
    const float4* Wg = (const float4*)(W + (size_t)h * 64 * 64);
    for (int i = tid; i < 1024; i += 256)
        ((float4*)Ws)[i] = Wg[i];

    // load 64-node agg tile into smem (padded stride)
    for (int i = tid; i < NPB * 16; i += 256) {
        int nd = i >> 4, j = i & 15;
        int n = n0 + nd;
        float4 v = make_float4(0.f, 0.f, 0.f, 0.f);
        if (n < NN) v = *(const float4*)(g_agg + (size_t)n * F + j * 4);
        *(float4*)(aggs + nd * AST + j * 4) = v;
    }
    __syncthreads();

    int o4 = (tid & 15) * 4;   // 4 consecutive outputs per thread
    int lane_nd = tid >> 4;    // 16 node lanes; each thread handles 4 nodes
    float acc[4][4];
#pragma unroll
    for (int k = 0; k < 4; k++)
#pragma unroll
        for (int q = 0; q < 4; q++) acc[k][q] = 0.f;

#pragma unroll 4
    for (int f = 0; f < 64; f++) {
        float4 w = *(const float4*)(Ws + f * 64 + o4);
#pragma unroll
        for (int k = 0; k < 4; k++) {
            float a = aggs[(lane_nd + 16 * k) * AST + f];
            acc[k][0] = fmaf(a, w.x, acc[k][0]);
            acc[k][1] = fmaf(a, w.y, acc[k][1]);
            acc[k][2] = fmaf(a, w.z, acc[k][2]);
            acc[k][3] = fmaf(a, w.w, acc[k][3]);
        }
    }

    float4 bv = *(const float4*)(b + h * 64 + o4);
#pragma unroll
    for (int k = 0; k < 4; k++) {
        int n = n0 + lane_nd + 16 * k;
        if (n >= NN) continue;
        float4 r;
        r.x = fmaxf(acc[k][0] + bv.x, 0.f);
        r.y = fmaxf(acc[k][1] + bv.y, 0.f);
        r.z = fmaxf(acc[k][2] + bv.z, 0.f);
        r.w = fmaxf(acc[k][3] + bv.w, 0.f);
        size_t off = (size_t)n * 256 + h * 64 + o4;
        *(float4*)(out + off) = r;
        if (dual) *(float4*)(out + (size_t)NN * 256 + off) = r;
    }
}

extern "C" void kernel_launch(void* const* d_in, const int* in_sizes, int n_in,
                              void* d_out, int out_size) {
    const float* x  = (const float*)d_in[0];
    const void*  ei = d_in[1];
    const float* W  = (const float*)d_in[2];
    const float* b  = (const float*)d_in[3];
    float* out = (float*)d_out;

    int dual = (out_size >= 2 * NN * 256) ? 1 : 0;

    k_sniff<<<1, 256>>>((const int*)ei);
    k_convert<<<(NE + 255) / 256, 256>>>(ei);
    k_deg_init<<<(NN + 255) / 256, 256>>>();
    k_deg_count<<<(NE + 255) / 256, 256>>>();
    k_prep<<<(NN * 16 + 255) / 256, 256>>>(x);
    k_scatter<<<(NE * 16) / 256, 256>>>();
    dim3 grid((NN + NPB - 1) / NPB, HEADS);
    k_gemm<<<grid, 256>>>(W, b, out, dual);
}

// round 4
// speedup vs baseline: 1.2799x; 1.2799x over previous
#include <cuda_runtime.h>

#define NN 50000
#define NE 1600000
#define F 64
#define DIN 256
#define HEADS 4
#define CAP 256
#define OVF_MAX 4096

// Scratch (device globals — no allocations allowed)
__device__ int g_is64;
__device__ int g_cursor[NN];              // per-node incoming-edge count (excl. self)
__device__ int g_ovf_cnt;
__device__ int g_ovf[OVF_MAX * 2];        // overflow edges (r,c)
__device__ __align__(16) int   g_bucket[(size_t)NN * CAP];  // row ids per col
__device__ __align__(16) float g_dinv[NN];
__device__ __align__(16) float g_xs[NN * F];   // x0 * dinv[src]
__device__ __align__(16) float g_agg[NN * F];  // aggregated features

// ---------------------------------------------------------------------------
// K0: sniff edge_index dtype. int64 LE values < 2^31 have all odd 32-bit words 0.
__global__ void k_sniff(const int* __restrict__ ei32) {
    __shared__ int nz;
    if (threadIdx.x == 0) nz = 0;
    __syncthreads();
    if (ei32[2 * threadIdx.x + 1] != 0) atomicAdd(&nz, 1);
    __syncthreads();
    if (threadIdx.x == 0) g_is64 = (nz < 8) ? 1 : 0;
}

// K1: zero cursors + overflow count
__global__ void k_zero() {
    int i = blockIdx.x * blockDim.x + threadIdx.x;
    if (i < NN) g_cursor[i] = 0;
    if (i == 0) g_ovf_cnt = 0;
}

// K2: fused convert + degree-count + bucket fill. One thread per edge.
__global__ void k_bucket(const void* __restrict__ ei) {
    int i = blockIdx.x * blockDim.x + threadIdx.x;
    if (i >= NE) return;
    int r, c;
    if (g_is64) {
        const long long* p = (const long long*)ei;
        r = (int)p[i];
        c = (int)p[NE + i];
    } else {
        const int* p = (const int*)ei;
        r = p[i];
        c = p[NE + i];
    }
    r = min(max(r, 0), NN - 1);
    c = min(max(c, 0), NN - 1);
    int pos = atomicAdd(&g_cursor[c], 1);
    if (pos < CAP) {
        g_bucket[(size_t)c * CAP + pos] = r;
    } else {
        int o = atomicAdd(&g_ovf_cnt, 1);
        if (o < OVF_MAX) { g_ovf[2 * o] = r; g_ovf[2 * o + 1] = c; }
    }
}

// K3: dinv = rsqrt(indeg+1); xs = x0 * dinv. One thread per (node, float4-chunk).
__global__ void k_prep(const float* __restrict__ x) {
    int i = blockIdx.x * blockDim.x + threadIdx.x;
    if (i >= NN * 16) return;
    int v = i >> 4, j = i & 15;
    float dinv = rsqrtf((float)(g_cursor[v] + 1));
    if (j == 0) g_dinv[v] = dinv;
    float4 xv = *(const float4*)(x + (size_t)v * DIN + j * 4);
    float4 xs;
    xs.x = xv.x * dinv; xs.y = xv.y * dinv; xs.z = xv.z * dinv; xs.w = xv.w * dinv;
    *(float4*)(g_xs + (size_t)v * F + j * 4) = xs;
}

// K4: gather. One warp per node; lanes 0-15 / 16-31 handle alternating edges,
// each lane owns one float4 chunk. agg[c] = dinv[c] * (xs[c] + sum xs[row]).
__global__ void k_gather() {
    int warp = (blockIdx.x * blockDim.x + threadIdx.x) >> 5;
    if (warp >= NN) return;
    int lane = threadIdx.x & 31;
    int j = lane & 15;
    int half = lane >> 4;
    int c = warp;
    int cnt = min(g_cursor[c], CAP);
    const int* __restrict__ bucket = g_bucket + (size_t)c * CAP;

    float4 acc = make_float4(0.f, 0.f, 0.f, 0.f);
    int k = half;
    // 2 edges in flight per half
    for (; k + 2 < cnt; k += 4) {
        int r0 = bucket[k];
        int r1 = bucket[k + 2];
        float4 m0 = *(const float4*)(g_xs + (size_t)r0 * F + j * 4);
        float4 m1 = *(const float4*)(g_xs + (size_t)r1 * F + j * 4);
        acc.x += m0.x + m1.x; acc.y += m0.y + m1.y;
        acc.z += m0.z + m1.z; acc.w += m0.w + m1.w;
    }
    for (; k < cnt; k += 2) {
        int r0 = bucket[k];
        float4 m0 = *(const float4*)(g_xs + (size_t)r0 * F + j * 4);
        acc.x += m0.x; acc.y += m0.y; acc.z += m0.z; acc.w += m0.w;
    }
    // combine the two halves
    acc.x += __shfl_xor_sync(0xffffffffu, acc.x, 16);
    acc.y += __shfl_xor_sync(0xffffffffu, acc.y, 16);
    acc.z += __shfl_xor_sync(0xffffffffu, acc.z, 16);
    acc.w += __shfl_xor_sync(0xffffffffu, acc.w, 16);

    if (half == 0) {
        float dinv = g_dinv[c];
        float4 s = *(const float4*)(g_xs + (size_t)c * F + j * 4);
        float4 o;
        o.x = dinv * (acc.x + s.x); o.y = dinv * (acc.y + s.y);
        o.z = dinv * (acc.z + s.z); o.w = dinv * (acc.w + s.w);
        *(float4*)(g_agg + (size_t)c * F + j * 4) = o;
    }
}

// K5: overflow fix-up (runs after gather; normally 0 edges). RED into agg.
__global__ void k_ovf_fix() {
    int n = min(g_ovf_cnt, OVF_MAX);
    for (int idx = threadIdx.x; idx < n * 16; idx += blockDim.x) {
        int e = idx >> 4, j = idx & 15;
        int r = g_ovf[2 * e], c = g_ovf[2 * e + 1];
        float s = g_dinv[c];
        float4 m = *(const float4*)(g_xs + (size_t)r * F + j * 4);
        float* dst = g_agg + (size_t)c * F + j * 4;
        asm volatile("red.global.add.v4.f32 [%0], {%1, %2, %3, %4};"
                     :: "l"(dst), "f"(m.x * s), "f"(m.y * s), "f"(m.z * s), "f"(m.w * s)
                     : "memory");
    }
}

// K6: heads = relu(agg @ W[h] + b[h]) with packed f32x2 FMA.
// One head per blockIdx.y; 64 nodes per block; agg stored duplicated in smem
// so the broadcast operand is a single LDS.64.
#define NPB 64
__global__ void k_gemm(const float* __restrict__ W, const float* __restrict__ b,
                       float* __restrict__ out, int dual) {
    __shared__ __align__(16) float Ws[64 * 64];            // 16KB
    __shared__ __align__(16) double Ad[NPB * 64];          // 32KB: (a,a) pairs
    int h = blockIdx.y;
    int n0 = blockIdx.x * NPB;
    int tid = threadIdx.x;

    const float4* Wg = (const float4*)(W + (size_t)h * 64 * 64);
    for (int i = tid; i < 1024; i += 256)
        ((float4*)Ws)[i] = Wg[i];

    for (int i = tid; i < NPB * 16; i += 256) {
        int nd = i >> 4, j = i & 15;
        int n = n0 + nd;
        float4 v = make_float4(0.f, 0.f, 0.f, 0.f);
        if (n < NN) v = *(const float4*)(g_agg + (size_t)n * F + j * 4);
        double* dst = Ad + nd * 64 + j * 4;
        dst[0] = __hiloint2double(__float_as_int(v.x), __float_as_int(v.x));
        dst[1] = __hiloint2double(__float_as_int(v.y), __float_as_int(v.y));
        dst[2] = __hiloint2double(__float_as_int(v.z), __float_as_int(v.z));
        dst[3] = __hiloint2double(__float_as_int(v.w), __float_as_int(v.w));
    }
    __syncthreads();

    int o4 = (tid & 15) * 4;   // 4 consecutive outputs per thread
    int lane_nd = tid >> 4;    // 16 node lanes; each thread handles 4 nodes
    unsigned long long acc[4][2];
#pragma unroll
    for (int k = 0; k < 4; k++) { acc[k][0] = 0ull; acc[k][1] = 0ull; }

#pragma unroll 4
    for (int f = 0; f < 64; f++) {
        double2 wd = *(const double2*)(Ws + f * 64 + o4);
        unsigned long long w0 = __double_as_longlong(wd.x);
        unsigned long long w1 = __double_as_longlong(wd.y);
#pragma unroll
        for (int k = 0; k < 4; k++) {
            unsigned long long a2 =
                __double_as_longlong(Ad[(lane_nd + 16 * k) * 64 + f]);
            asm("fma.rn.f32x2 %0, %1, %2, %0;" : "+l"(acc[k][0]) : "l"(a2), "l"(w0));
            asm("fma.rn.f32x2 %0, %1, %2, %0;" : "+l"(acc[k][1]) : "l"(a2), "l"(w1));
        }
    }

    float4 bv = *(const float4*)(b + h * 64 + o4);
#pragma unroll
    for (int k = 0; k < 4; k++) {
        int n = n0 + lane_nd + 16 * k;
        if (n >= NN) continue;
        float4 r;
        r.x = fmaxf(__uint_as_float((unsigned)(acc[k][0] & 0xffffffffull)) + bv.x, 0.f);
        r.y = fmaxf(__uint_as_float((unsigned)(acc[k][0] >> 32)) + bv.y, 0.f);
        r.z = fmaxf(__uint_as_float((unsigned)(acc[k][1] & 0xffffffffull)) + bv.z, 0.f);
        r.w = fmaxf(__uint_as_float((unsigned)(acc[k][1] >> 32)) + bv.w, 0.f);
        size_t off = (size_t)n * 256 + h * 64 + o4;
        *(float4*)(out + off) = r;
        if (dual) *(float4*)(out + (size_t)NN * 256 + off) = r;
    }
}

extern "C" void kernel_launch(void* const* d_in, const int* in_sizes, int n_in,
                              void* d_out, int out_size) {
    const float* x  = (const float*)d_in[0];
    const void*  ei = d_in[1];
    const float* W  = (const float*)d_in[2];
    const float* b  = (const float*)d_in[3];
    float* out = (float*)d_out;

    int dual = (out_size >= 2 * NN * 256) ? 1 : 0;

    k_sniff<<<1, 256>>>((const int*)ei);
    k_zero<<<(NN + 255) / 256, 256>>>();
    k_bucket<<<(NE + 255) / 256, 256>>>(ei);
    k_prep<<<(NN * 16 + 255) / 256, 256>>>(x);
    k_gather<<<(NN * 32 + 255) / 256, 256>>>();
    k_ovf_fix<<<1, 256>>>();
    dim3 grid((NN + NPB - 1) / NPB, HEADS);
    k_gemm<<<grid, 256>>>(W, b, out, dual);
}

// round 5
// speedup vs baseline: 1.3489x; 1.0539x over previous
#include <cuda_runtime.h>
#include <cuda_fp16.h>

#define NN 50000
#define NE 1600000
#define F 64
#define DIN 256
#define HEADS 4
#define CAP 256
#define OVF_MAX 4096

// Scratch (device globals — no allocations allowed)
__device__ int g_is64;
__device__ int g_cursor[NN];              // per-node incoming-edge count (excl. self)
__device__ int g_ovf_cnt;
__device__ int g_ovf[OVF_MAX * 2];        // overflow edges (r,c)
__device__ __align__(16) int    g_bucket[(size_t)NN * CAP];  // row ids per col
__device__ __align__(16) float  g_dinv[NN];
__device__ __align__(16) __half g_xs[(size_t)NN * F];  // fp16: x0 * dinv[src]
__device__ __align__(16) float  g_agg[NN * F];         // aggregated features (fp32)

// ---------------------------------------------------------------------------
// K1: zero cursors + overflow count; block 0 also sniffs edge dtype
// (int64 LE values < 2^31 have all odd 32-bit words == 0).
__global__ void k_init(const int* __restrict__ ei32) {
    int i = blockIdx.x * blockDim.x + threadIdx.x;
    if (i < NN) g_cursor[i] = 0;
    if (i == 0) g_ovf_cnt = 0;
    if (blockIdx.x == 0) {
        __shared__ int nz;
        if (threadIdx.x == 0) nz = 0;
        __syncthreads();
        if (ei32[2 * threadIdx.x + 1] != 0) atomicAdd(&nz, 1);
        __syncthreads();
        if (threadIdx.x == 0) g_is64 = (nz < 8) ? 1 : 0;
    }
}

// K2: fused convert + degree-count + bucket fill. One thread per edge.
__global__ void k_bucket(const void* __restrict__ ei) {
    int i = blockIdx.x * blockDim.x + threadIdx.x;
    if (i >= NE) return;
    int r, c;
    if (g_is64) {
        const long long* p = (const long long*)ei;
        r = (int)p[i];
        c = (int)p[NE + i];
    } else {
        const int* p = (const int*)ei;
        r = p[i];
        c = p[NE + i];
    }
    r = min(max(r, 0), NN - 1);
    c = min(max(c, 0), NN - 1);
    int pos = atomicAdd(&g_cursor[c], 1);
    if (pos < CAP) {
        g_bucket[(size_t)c * CAP + pos] = r;
    } else {
        int o = atomicAdd(&g_ovf_cnt, 1);
        if (o < OVF_MAX) { g_ovf[2 * o] = r; g_ovf[2 * o + 1] = c; }
    }
}

// K3: dinv = rsqrt(indeg+1); xs = fp16(x0 * dinv). One thread per (node, 4-feature chunk).
__global__ void k_prep(const float* __restrict__ x) {
    int i = blockIdx.x * blockDim.x + threadIdx.x;
    if (i >= NN * 16) return;
    int v = i >> 4, j = i & 15;
    float dinv = rsqrtf((float)(g_cursor[v] + 1));
    if (j == 0) g_dinv[v] = dinv;
    float4 xv = *(const float4*)(x + (size_t)v * DIN + j * 4);
    __half2 h0 = __floats2half2_rn(xv.x * dinv, xv.y * dinv);
    __half2 h1 = __floats2half2_rn(xv.z * dinv, xv.w * dinv);
    uint2 u = make_uint2(*(unsigned*)&h0, *(unsigned*)&h1);
    *(uint2*)(g_xs + (size_t)v * F + j * 4) = u;
}

__device__ __forceinline__ void acc_xs(float4& acc, int r, int j) {
    uint2 u = *(const uint2*)(g_xs + (size_t)r * F + j * 4);
    float2 fa = __half22float2(*(__half2*)&u.x);
    float2 fb = __half22float2(*(__half2*)&u.y);
    acc.x += fa.x; acc.y += fa.y; acc.z += fb.x; acc.w += fb.y;
}

// K4: gather. One warp per node; halves (lanes 0-15 / 16-31) take alternating
// edges, each lane owns 4 features. agg[c] = dinv[c] * (xs[c] + sum xs[row]).
__global__ void k_gather() {
    int warp = (blockIdx.x * blockDim.x + threadIdx.x) >> 5;
    if (warp >= NN) return;
    int lane = threadIdx.x & 31;
    int j = lane & 15;
    int half = lane >> 4;
    int c = warp;
    int cnt = min(g_cursor[c], CAP);
    const int* __restrict__ bucket = g_bucket + (size_t)c * CAP;

    float4 acc = make_float4(0.f, 0.f, 0.f, 0.f);
    int k = half;
    // 4 edges in flight per half
    for (; k + 6 < cnt; k += 8) {
        int r0 = bucket[k];
        int r1 = bucket[k + 2];
        int r2 = bucket[k + 4];
        int r3 = bucket[k + 6];
        acc_xs(acc, r0, j);
        acc_xs(acc, r1, j);
        acc_xs(acc, r2, j);
        acc_xs(acc, r3, j);
    }
    for (; k < cnt; k += 2)
        acc_xs(acc, bucket[k], j);

    // combine the two halves
    acc.x += __shfl_xor_sync(0xffffffffu, acc.x, 16);
    acc.y += __shfl_xor_sync(0xffffffffu, acc.y, 16);
    acc.z += __shfl_xor_sync(0xffffffffu, acc.z, 16);
    acc.w += __shfl_xor_sync(0xffffffffu, acc.w, 16);

    if (half == 0) {
        float dinv = g_dinv[c];
        float4 s = make_float4(0.f, 0.f, 0.f, 0.f);
        acc_xs(s, c, j);  // self-loop term
        float4 o;
        o.x = dinv * (acc.x + s.x); o.y = dinv * (acc.y + s.y);
        o.z = dinv * (acc.z + s.z); o.w = dinv * (acc.w + s.w);
        *(float4*)(g_agg + (size_t)c * F + j * 4) = o;
    }
}

// K5: overflow fix-up (normally 0 edges). RED into agg.
__global__ void k_ovf_fix() {
    int n = min(g_ovf_cnt, OVF_MAX);
    for (int idx = threadIdx.x; idx < n * 16; idx += blockDim.x) {
        int e = idx >> 4, j = idx & 15;
        int r = g_ovf[2 * e], c = g_ovf[2 * e + 1];
        float s = g_dinv[c];
        float4 m = make_float4(0.f, 0.f, 0.f, 0.f);
        acc_xs(m, r, j);
        float* dst = g_agg + (size_t)c * F + j * 4;
        asm volatile("red.global.add.v4.f32 [%0], {%1, %2, %3, %4};"
                     :: "l"(dst), "f"(m.x * s), "f"(m.y * s), "f"(m.z * s), "f"(m.w * s)
                     : "memory");
    }
}

// K6: heads = relu(agg @ W[h] + b[h]) with packed f32x2 FMA.
// One head per blockIdx.y; 64 nodes per block; agg stored duplicated in smem
// so the broadcast operand is a single LDS.64.
#define NPB 64
__global__ void k_gemm(const float* __restrict__ W, const float* __restrict__ b,
                       float* __restrict__ out, int dual) {
    __shared__ __align__(16) float Ws[64 * 64];            // 16KB
    __shared__ __align__(16) double Ad[NPB * 64];          // 32KB: (a,a) pairs
    int h = blockIdx.y;
    int n0 = blockIdx.x * NPB;
    int tid = threadIdx.x;

    const float4* Wg = (const float4*)(W + (size_t)h * 64 * 64);
    for (int i = tid; i < 1024; i += 256)
        ((float4*)Ws)[i] = Wg[i];

    for (int i = tid; i < NPB * 16; i += 256) {
        int nd = i >> 4, j = i & 15;
        int n = n0 + nd;
        float4 v = make_float4(0.f, 0.f, 0.f, 0.f);
        if (n < NN) v = *(const float4*)(g_agg + (size_t)n * F + j * 4);
        double* dst = Ad + nd * 64 + j * 4;
        dst[0] = __hiloint2double(__float_as_int(v.x), __float_as_int(v.x));
        dst[1] = __hiloint2double(__float_as_int(v.y), __float_as_int(v.y));
        dst[2] = __hiloint2double(__float_as_int(v.z), __float_as_int(v.z));
        dst[3] = __hiloint2double(__float_as_int(v.w), __float_as_int(v.w));
    }
    __syncthreads();

    int o4 = (tid & 15) * 4;   // 4 consecutive outputs per thread
    int lane_nd = tid >> 4;    // 16 node lanes; each thread handles 4 nodes
    unsigned long long acc[4][2];
#pragma unroll
    for (int k = 0; k < 4; k++) { acc[k][0] = 0ull; acc[k][1] = 0ull; }

#pragma unroll 4
    for (int f = 0; f < 64; f++) {
        double2 wd = *(const double2*)(Ws + f * 64 + o4);
        unsigned long long w0 = __double_as_longlong(wd.x);
        unsigned long long w1 = __double_as_longlong(wd.y);
#pragma unroll
        for (int k = 0; k < 4; k++) {
            unsigned long long a2 =
                __double_as_longlong(Ad[(lane_nd + 16 * k) * 64 + f]);
            asm("fma.rn.f32x2 %0, %1, %2, %0;" : "+l"(acc[k][0]) : "l"(a2), "l"(w0));
            asm("fma.rn.f32x2 %0, %1, %2, %0;" : "+l"(acc[k][1]) : "l"(a2), "l"(w1));
        }
    }

    float4 bv = *(const float4*)(b + h * 64 + o4);
#pragma unroll
    for (int k = 0; k < 4; k++) {
        int n = n0 + lane_nd + 16 * k;
        if (n >= NN) continue;
        float4 r;
        r.x = fmaxf(__uint_as_float((unsigned)(acc[k][0] & 0xffffffffull)) + bv.x, 0.f);
        r.y = fmaxf(__uint_as_float((unsigned)(acc[k][0] >> 32)) + bv.y, 0.f);
        r.z = fmaxf(__uint_as_float((unsigned)(acc[k][1] & 0xffffffffull)) + bv.z, 0.f);
        r.w = fmaxf(__uint_as_float((unsigned)(acc[k][1] >> 32)) + bv.w, 0.f);
        size_t off = (size_t)n * 256 + h * 64 + o4;
        *(float4*)(out + off) = r;
        if (dual) *(float4*)(out + (size_t)NN * 256 + off) = r;
    }
}

extern "C" void kernel_launch(void* const* d_in, const int* in_sizes, int n_in,
                              void* d_out, int out_size) {
    const float* x  = (const float*)d_in[0];
    const void*  ei = d_in[1];
    const float* W  = (const float*)d_in[2];
    const float* b  = (const float*)d_in[3];
    float* out = (float*)d_out;

    int dual = (out_size >= 2 * NN * 256) ? 1 : 0;

    k_init<<<(NN + 255) / 256, 256>>>((const int*)ei);
    k_bucket<<<(NE + 255) / 256, 256>>>(ei);
    k_prep<<<(NN * 16 + 255) / 256, 256>>>(x);
    k_gather<<<(NN * 32 + 255) / 256, 256>>>();
    k_ovf_fix<<<1, 256>>>();
    dim3 grid((NN + NPB - 1) / NPB, HEADS);
    k_gemm<<<grid, 256>>>(W, b, out, dual);
}

// round 17
// speedup vs baseline: 1.3882x; 1.0292x over previous
#include <cuda_runtime.h>
#include <cuda_fp16.h>

#define NN 50000
#define NE 1600000
#define F 64
#define DIN 256
#define HEADS 4
#define CAP 256
#define OVF_MAX 4096

// Scratch (device globals — no allocations allowed)
__device__ int g_is64;
__device__ int g_cursor[NN];              // per-node incoming-edge count (excl. self)
__device__ int g_ovf_cnt;
__device__ int g_ovf[OVF_MAX * 2];        // overflow edges (r,c)
__device__ __align__(16) int    g_bucket[(size_t)NN * CAP];  // row ids per col
__device__ __align__(16) float  g_dinv[NN];
__device__ __align__(16) __half g_xs[(size_t)NN * F];  // fp16: x0 * dinv[src]
__device__ __align__(16) float  g_agg[NN * F];         // aggregated features (fp32)

// ---------------------------------------------------------------------------
// K1: zero cursors + overflow count; block 0 also sniffs edge dtype
// (int64 LE values < 2^31 have all odd 32-bit words == 0).
__global__ void k_init(const int* __restrict__ ei32) {
    int i = blockIdx.x * blockDim.x + threadIdx.x;
    if (i < NN) g_cursor[i] = 0;
    if (i == 0) g_ovf_cnt = 0;
    if (blockIdx.x == 0) {
        __shared__ int nz;
        if (threadIdx.x == 0) nz = 0;
        __syncthreads();
        if (ei32[2 * threadIdx.x + 1] != 0) atomicAdd(&nz, 1);
        __syncthreads();
        if (threadIdx.x == 0) g_is64 = (nz < 8) ? 1 : 0;
    }
}

// K2: fused convert + degree-count + bucket fill. Two edges per thread.
__global__ void k_bucket(const void* __restrict__ ei) {
    int i = (blockIdx.x * blockDim.x + threadIdx.x) * 2;
    if (i >= NE) return;
    int r0, c0, r1, c1;
    if (g_is64) {
        const int4* pr = (const int4*)((const long long*)ei + i);
        const int4* pc = (const int4*)((const long long*)ei + NE + i);
        int4 rv = *pr, cv = *pc;
        r0 = rv.x; r1 = rv.z; c0 = cv.x; c1 = cv.z;
    } else {
        const int2 rv = *(const int2*)((const int*)ei + i);
        const int2 cv = *(const int2*)((const int*)ei + NE + i);
        r0 = rv.x; r1 = rv.y; c0 = cv.x; c1 = cv.y;
    }
    r0 = min(max(r0, 0), NN - 1); c0 = min(max(c0, 0), NN - 1);
    r1 = min(max(r1, 0), NN - 1); c1 = min(max(c1, 0), NN - 1);
    int p0 = atomicAdd(&g_cursor[c0], 1);
    if (p0 < CAP) g_bucket[(size_t)c0 * CAP + p0] = r0;
    else { int o = atomicAdd(&g_ovf_cnt, 1); if (o < OVF_MAX) { g_ovf[2*o] = r0; g_ovf[2*o+1] = c0; } }
    int p1 = atomicAdd(&g_cursor[c1], 1);
    if (p1 < CAP) g_bucket[(size_t)c1 * CAP + p1] = r1;
    else { int o = atomicAdd(&g_ovf_cnt, 1); if (o < OVF_MAX) { g_ovf[2*o] = r1; g_ovf[2*o+1] = c1; } }
}

// K3: dinv = rsqrt(indeg+1); xs = fp16(x0 * dinv). One thread per (node, 2x float4 chunk).
__global__ void k_prep(const float* __restrict__ x) {
    int i = blockIdx.x * blockDim.x + threadIdx.x;
    if (i >= NN * 8) return;
    int v = i >> 3, j = i & 7;   // j chunk and j+8 chunk
    float dinv = rsqrtf((float)(g_cursor[v] + 1));
    if (j == 0) g_dinv[v] = dinv;
    float4 xa = *(const float4*)(x + (size_t)v * DIN + j * 4);
    float4 xb = *(const float4*)(x + (size_t)v * DIN + (j + 8) * 4);
    __half2 a0 = __floats2half2_rn(xa.x * dinv, xa.y * dinv);
    __half2 a1 = __floats2half2_rn(xa.z * dinv, xa.w * dinv);
    __half2 b0 = __floats2half2_rn(xb.x * dinv, xb.y * dinv);
    __half2 b1 = __floats2half2_rn(xb.z * dinv, xb.w * dinv);
    *(uint2*)(g_xs + (size_t)v * F + j * 4) = make_uint2(*(unsigned*)&a0, *(unsigned*)&a1);
    *(uint2*)(g_xs + (size_t)v * F + (j + 8) * 4) = make_uint2(*(unsigned*)&b0, *(unsigned*)&b1);
}

__device__ __forceinline__ void acc_u(float4& acc, uint2 u) {
    float2 fa = __half22float2(*(__half2*)&u.x);
    float2 fb = __half22float2(*(__half2*)&u.y);
    acc.x += fa.x; acc.y += fa.y; acc.z += fb.x; acc.w += fb.y;
}
__device__ __forceinline__ uint2 ld_xs(int r, int j) {
    return *(const uint2*)(g_xs + (size_t)r * F + j * 4);
}

// K4: gather. One warp per node; halves (lanes 0-15 / 16-31) take alternating
// edges, each lane owns 4 features. 8 edges in flight per half.
// agg[c] = dinv[c] * (xs[c] + sum xs[row]). Overflow handled inline.
__global__ void __launch_bounds__(256) k_gather() {
    int warp = (blockIdx.x * blockDim.x + threadIdx.x) >> 5;
    if (warp >= NN) return;
    int lane = threadIdx.x & 31;
    int j = lane & 15;
    int half = lane >> 4;
    int c = warp;
    int cntRaw = g_cursor[c];
    int cnt = min(cntRaw, CAP);
    const int* __restrict__ bucket = g_bucket + (size_t)c * CAP;

    float4 acc0 = make_float4(0.f, 0.f, 0.f, 0.f);
    float4 acc1 = make_float4(0.f, 0.f, 0.f, 0.f);
    int k = half;
    for (; k + 14 < cnt; k += 16) {
        int r0 = bucket[k],      r1 = bucket[k + 2],  r2 = bucket[k + 4],  r3 = bucket[k + 6];
        int r4 = bucket[k + 8],  r5 = bucket[k + 10], r6 = bucket[k + 12], r7 = bucket[k + 14];
        uint2 u0 = ld_xs(r0, j), u1 = ld_xs(r1, j), u2 = ld_xs(r2, j), u3 = ld_xs(r3, j);
        uint2 u4 = ld_xs(r4, j), u5 = ld_xs(r5, j), u6 = ld_xs(r6, j), u7 = ld_xs(r7, j);
        acc_u(acc0, u0); acc_u(acc1, u1); acc_u(acc0, u2); acc_u(acc1, u3);
        acc_u(acc0, u4); acc_u(acc1, u5); acc_u(acc0, u6); acc_u(acc1, u7);
    }
    for (; k < cnt; k += 2)
        acc_u(acc0, ld_xs(bucket[k], j));

    // overflow entries (normally none): only cols that overflowed scan the list
    if (cntRaw > CAP) {
        int ovf_n = min(g_ovf_cnt, OVF_MAX);
        for (int o = half; o < ovf_n; o += 2) {
            if (g_ovf[2 * o + 1] == c)
                acc_u(acc0, ld_xs(g_ovf[2 * o], j));
        }
    }

    float4 acc;
    acc.x = acc0.x + acc1.x; acc.y = acc0.y + acc1.y;
    acc.z = acc0.z + acc1.z; acc.w = acc0.w + acc1.w;
    acc.x += __shfl_xor_sync(0xffffffffu, acc.x, 16);
    acc.y += __shfl_xor_sync(0xffffffffu, acc.y, 16);
    acc.z += __shfl_xor_sync(0xffffffffu, acc.z, 16);
    acc.w += __shfl_xor_sync(0xffffffffu, acc.w, 16);

    if (half == 0) {
        float dinv = g_dinv[c];
        float4 s = make_float4(0.f, 0.f, 0.f, 0.f);
        acc_u(s, ld_xs(c, j));  // self-loop term
        float4 o;
        o.x = dinv * (acc.x + s.x); o.y = dinv * (acc.y + s.y);
        o.z = dinv * (acc.z + s.z); o.w = dinv * (acc.w + s.w);
        *(float4*)(g_agg + (size_t)c * F + j * 4) = o;
    }
}

// K5: heads = relu(agg @ W[h] + b[h]) with packed f32x2 FMA.
// One head per blockIdx.y; 64 nodes per block; agg stored duplicated in smem
// so the broadcast operand is a single LDS.64.
#define NPB 64
__global__ void k_gemm(const float* __restrict__ W, const float* __restrict__ b,
                       float* __restrict__ out, int dual) {
    __shared__ __align__(16) float Ws[64 * 64];            // 16KB
    __shared__ __align__(16) double Ad[NPB * 64];          // 32KB: (a,a) pairs
    int h = blockIdx.y;
    int n0 = blockIdx.x * NPB;
    int tid = threadIdx.x;

    const float4* Wg = (const float4*)(W + (size_t)h * 64 * 64);
    for (int i = tid; i < 1024; i += 256)
        ((float4*)Ws)[i] = Wg[i];

    for (int i = tid; i < NPB * 16; i += 256) {
        int nd = i >> 4, j = i & 15;
        int n = n0 + nd;
        float4 v = make_float4(0.f, 0.f, 0.f, 0.f);
        if (n < NN) v = *(const float4*)(g_agg + (size_t)n * F + j * 4);
        double* dst = Ad + nd * 64 + j * 4;
        dst[0] = __hiloint2double(__float_as_int(v.x), __float_as_int(v.x));
        dst[1] = __hiloint2double(__float_as_int(v.y), __float_as_int(v.y));
        dst[2] = __hiloint2double(__float_as_int(v.z), __float_as_int(v.z));
        dst[3] = __hiloint2double(__float_as_int(v.w), __float_as_int(v.w));
    }
    __syncthreads();

    int o4 = (tid & 15) * 4;   // 4 consecutive outputs per thread
    int lane_nd = tid >> 4;    // 16 node lanes; each thread handles 4 nodes
    unsigned long long acc[4][2];
#pragma unroll
    for (int k = 0; k < 4; k++) { acc[k][0] = 0ull; acc[k][1] = 0ull; }

#pragma unroll 4
    for (int f = 0; f < 64; f++) {
        double2 wd = *(const double2*)(Ws + f * 64 + o4);
        unsigned long long w0 = __double_as_longlong(wd.x);
        unsigned long long w1 = __double_as_longlong(wd.y);
#pragma unroll
        for (int k = 0; k < 4; k++) {
            unsigned long long a2 =
                __double_as_longlong(Ad[(lane_nd + 16 * k) * 64 + f]);
            asm("fma.rn.f32x2 %0, %1, %2, %0;" : "+l"(acc[k][0]) : "l"(a2), "l"(w0));
            asm("fma.rn.f32x2 %0, %1, %2, %0;" : "+l"(acc[k][1]) : "l"(a2), "l"(w1));
        }
    }

    float4 bv = *(const float4*)(b + h * 64 + o4);
#pragma unroll
    for (int k = 0; k < 4; k++) {
        int n = n0 + lane_nd + 16 * k;
        if (n >= NN) continue;
        float4 r;
        r.x = fmaxf(__uint_as_float((unsigned)(acc[k][0] & 0xffffffffull)) + bv.x, 0.f);
        r.y = fmaxf(__uint_as_float((unsigned)(acc[k][0] >> 32)) + bv.y, 0.f);
        r.z = fmaxf(__uint_as_float((unsigned)(acc[k][1] & 0xffffffffull)) + bv.z, 0.f);
        r.w = fmaxf(__uint_as_float((unsigned)(acc[k][1] >> 32)) + bv.w, 0.f);
        size_t off = (size_t)n * 256 + h * 64 + o4;
        *(float4*)(out + off) = r;
        if (dual) *(float4*)(out + (size_t)NN * 256 + off) = r;
    }
}

extern "C" void kernel_launch(void* const* d_in, const int* in_sizes, int n_in,
                              void* d_out, int out_size) {
    const float* x  = (const float*)d_in[0];
    const void*  ei = d_in[1];
    const float* W  = (const float*)d_in[2];
    const float* b  = (const float*)d_in[3];
    float* out = (float*)d_out;

    int dual = (out_size >= 2 * NN * 256) ? 1 : 0;

    k_init<<<(NN + 255) / 256, 256>>>((const int*)ei);
    k_bucket<<<(NE / 2 + 255) / 256, 256>>>(ei);
    k_prep<<<(NN * 8 + 255) / 256, 256>>>(x);
    k_gather<<<(NN * 32 + 255) / 256, 256>>>();
    dim3 grid((NN + NPB - 1) / NPB, HEADS);
    k_gemm<<<grid, 256>>>(W, b, out, dual);
}